// round 8
// baseline (speedup 1.0000x reference)
#include <cuda_runtime.h>
#include <cuda_fp16.h>
#include <cstdint>
#include <cstddef>

#define BS 8
#define CI 256
#define CO 256
#define HH 128
#define WW 128
#define EPSV 1e-6f

#define CKN 16                    // ci chunks of 16
// Stage layout (halves):
//  X: [xrow 4][pix 130 padded][16 slots] = 8320 halves (16640 B)
//  W: [tap 5][co 128][16 slots]          = 10240 halves (20480 B)
#define XROWH 2080
#define XH (4 * XROWH)            // 8320
#define WH 10240
#define STAGEH (XH + WH)          // 18560 halves = 37120 B
#define NSTAGE 4
#define TXBYTES (STAGEH * 2)
#define SMEM_DYN (NSTAGE * STAGEH * 2 + 256)

// ---------------- device scratch (no cudaMalloc allowed) ----------------
// x: fp16, padded, slot-interleaved: block (b*16+ck)*128+h of 2080 halves:
//    [pix 0..129][slot 16]; slot pairs p: p=2t -> ci(2t,2t+1), p=2t+1 -> ci(2t+8,2t+9)
__device__ __align__(16) __half g_xt[(size_t)BS * CKN * HH * XROWH];
// w_eff = fp16(w * (1+y) * demod): block ((b*2+ct)*16+ck): [tap][co][slot 16]
__device__ __align__(16) __half g_weff[(size_t)BS * 2 * CKN * WH];
__device__ float g_demod[BS * CO];
__device__ __align__(16) __half g_zero[XROWH];   // zero halo row (.bss)

// ---------------- PTX helpers (base sm_103 legal; NO tcgen05) ----------------
__device__ __forceinline__ uint32_t smem_u32(const void* p) {
    uint32_t a;
    asm("{ .reg .u64 t; cvta.to.shared.u64 t, %1; cvt.u32.u64 %0, t; }" : "=r"(a) : "l"(p));
    return a;
}
__device__ __forceinline__ void mbar_init(uint32_t mbar, uint32_t cnt) {
    asm volatile("mbarrier.init.shared.b64 [%0], %1;" :: "r"(mbar), "r"(cnt) : "memory");
}
__device__ __forceinline__ void mbar_expect_tx(uint32_t mbar, uint32_t bytes) {
    asm volatile("mbarrier.arrive.expect_tx.shared.b64 _, [%0], %1;"
                 :: "r"(mbar), "r"(bytes) : "memory");
}
__device__ __forceinline__ void mbar_arrive(uint32_t mbar) {
    asm volatile("mbarrier.arrive.shared.b64 _, [%0];" :: "r"(mbar) : "memory");
}
__device__ __forceinline__ void mbar_wait(uint32_t mbar, uint32_t parity) {
    asm volatile(
        "{\n\t.reg .pred P;\n\t"
        "WL_%=:\n\t"
        "mbarrier.try_wait.parity.acquire.cta.shared::cta.b64 P, [%0], %1, 0x989680;\n\t"
        "@P bra.uni WD_%=;\n\t"
        "bra.uni WL_%=;\n\t"
        "WD_%=:\n\t}"
        :: "r"(mbar), "r"(parity) : "memory");
}
__device__ __forceinline__ void bulk_g2s(uint32_t dst, const void* src, uint32_t bytes, uint32_t mbar) {
    asm volatile(
        "cp.async.bulk.shared::cluster.global.mbarrier::complete_tx::bytes [%0], [%1], %2, [%3];"
        :: "r"(dst), "l"(src), "r"(bytes), "r"(mbar) : "memory");
}
__device__ __forceinline__ void fence_async() {
    asm volatile("fence.proxy.async.shared::cta;" ::: "memory");
}
// m16n8k16 fp16 MMA, fp32 accumulate
__device__ __forceinline__ void mma16(float* d, const uint32_t* a, uint32_t b0, uint32_t b1) {
    asm volatile(
        "mma.sync.aligned.m16n8k16.row.col.f32.f16.f16.f32 "
        "{%0,%1,%2,%3}, {%4,%5,%6,%7}, {%8,%9}, {%0,%1,%2,%3};"
        : "+f"(d[0]), "+f"(d[1]), "+f"(d[2]), "+f"(d[3])
        : "r"(a[0]), "r"(a[1]), "r"(a[2]), "r"(a[3]), "r"(b0), "r"(b1));
}

// ---------------- prologue: demod ----------------
__global__ void demod_kernel(const float* __restrict__ y, const float* __restrict__ w) {
    int o = blockIdx.x, b = blockIdx.y, ci = threadIdx.x;
    float m = 1.0f + y[b * CI + ci];
    const float* wr = w + ((size_t)o * CI + ci) * 5;
    float s = wr[0]*wr[0] + wr[1]*wr[1] + wr[2]*wr[2] + wr[3]*wr[3] + wr[4]*wr[4];
    float v = m * m * s;
#pragma unroll
    for (int off = 16; off; off >>= 1) v += __shfl_xor_sync(0xffffffffu, v, off);
    __shared__ float red[8];
    if ((threadIdx.x & 31) == 0) red[threadIdx.x >> 5] = v;
    __syncthreads();
    if (threadIdx.x == 0) {
        float t = red[0]+red[1]+red[2]+red[3]+red[4]+red[5]+red[6]+red[7];
        g_demod[b * CO + o] = rsqrtf(t + EPSV);
    }
}

// ---------------- prologue: x -> fp16, transpose, pad, slot-interleave ----------------
__global__ __launch_bounds__(256) void prep_x_kernel(const float* __restrict__ x) {
    __shared__ float xs[16][132];
    const int t = threadIdx.x;
    const int h = blockIdx.x, ck = blockIdx.y, b = blockIdx.z;

    const float* src = x + ((size_t)(b * CI + ck * 16) * HH + h) * WW;
#pragma unroll
    for (int r = 0; r < 8; r++) {
        int idx = t + r * 256;
        int j = idx >> 7, pix = idx & 127;
        xs[j][pix] = src[(size_t)j * HH * WW + pix];
    }
    __syncthreads();

    __half2* dst = (__half2*)(g_xt + ((size_t)((b * CKN + ck) * HH + h)) * XROWH);
#pragma unroll
    for (int r = 0; r < 4; r++) {
        int o = t + r * 256;               // 0..1023: pix*8 + pairslot
        int pix = o >> 3, p = o & 7;
        int ci0 = ((p >> 1) << 1) + ((p & 1) << 3);   // p=2t -> 2t ; p=2t+1 -> 2t+8
        dst[(pix + 1) * 8 + p] = __floats2half2_rn(xs[ci0][pix], xs[ci0 + 1][pix]);
    }
    if (t < 16) {   // zero borders: pix 0 and 129
        int side = t >> 3, p = t & 7;
        dst[(side ? 129 : 0) * 8 + p] = __floats2half2_rn(0.f, 0.f);
    }
}

// ---------------- prologue: modulated+demodulated fp16 weights (SMEM layout) ----------
__global__ __launch_bounds__(128) void prep_w_kernel(
    const float* __restrict__ w, const float* __restrict__ y)
{
    const int ck = blockIdx.x, ct = blockIdx.y, b = blockIdx.z;
    const int co = threadIdx.x;
    const int o = ct * 128 + co;
    const float dd = g_demod[b * CO + o];
    __half2* blk = (__half2*)(g_weff + ((size_t)((b * 2 + ct) * CKN + ck)) * WH);
#pragma unroll
    for (int p = 0; p < 8; p++) {
        const int j0 = ((p >> 1) << 1) + ((p & 1) << 3);
        const int ci0 = ck * 16 + j0;
        const float m0 = (1.0f + y[b * CI + ci0]) * dd;
        const float m1 = (1.0f + y[b * CI + ci0 + 1]) * dd;
        const float* wp0 = w + ((size_t)o * CI + ci0) * 5;
        const float* wp1 = wp0 + 5;
#pragma unroll
        for (int tap = 0; tap < 5; tap++)
            blk[(tap * 128 + co) * 8 + p] = __floats2half2_rn(wp0[tap] * m0, wp1[tap] * m1);
    }
}

// ---------------- producer: one chunk into a stage ----------------
__device__ __forceinline__ void issue_chunk(
    int c, int h0, int b, int ct, uint32_t stage_dst, uint32_t full_mb)
{
    mbar_expect_tx(full_mb, TXBYTES);
    const __half* xb = g_xt + ((size_t)(b * CKN + c) * HH) * XROWH;
    if (h0 >= 2 && h0 <= 124) {
        bulk_g2s(stage_dst, xb + (size_t)(h0 - 1) * XROWH, 4 * XROWH * 2, full_mb);
    } else if (h0 == 0) {
        bulk_g2s(stage_dst, g_zero, XROWH * 2, full_mb);
        bulk_g2s(stage_dst + XROWH * 2, xb, 3 * XROWH * 2, full_mb);
    } else { // h0 == 126
        bulk_g2s(stage_dst, xb + (size_t)125 * XROWH, 3 * XROWH * 2, full_mb);
        bulk_g2s(stage_dst + 3 * XROWH * 2, g_zero, XROWH * 2, full_mb);
    }
    bulk_g2s(stage_dst + XH * 2,
             g_weff + ((size_t)((b * 2 + ct) * CKN + c)) * WH, WH * 2, full_mb);
}

// ---------------- main: fp16 mma.sync, 256 thr, warp M64xN64, 4 stages --------------
__global__ __launch_bounds__(256, 1) void conv_mma_kernel(float* __restrict__ out) {
    extern __shared__ __half smem[];
    const uint32_t smem_base = smem_u32(smem);
    const uint32_t barbase = smem_base + NSTAGE * STAGEH * 2;

    const int tid  = threadIdx.x;
    const int lane = tid & 31;
    const int wid  = tid >> 5;
    const int grp  = lane >> 2;
    const int tig  = lane & 3;
    const int mg = wid >> 1;             // 0..3 : M64 tile over M=256
    const int ng = wid & 1;              // 0..1 : N64 tile over N=128
    const int row = mg >> 1;             // output row within CTA (0/1)
    const int pbase = (mg & 1) * 64;     // pixel base

    const int h0 = blockIdx.x * 2;
    const int ct = blockIdx.y;
    const int b  = blockIdx.z;

    if (tid == 0) {
        for (int s = 0; s < NSTAGE; s++) {
            mbar_init(barbase + s * 8, 1);                   // full
            mbar_init(barbase + NSTAGE * 8 + s * 8, 8);      // empty (per warp)
        }
        fence_async();
    }
    __syncthreads();
    if (tid == 0)
        for (int c = 0; c < NSTAGE; c++)
            issue_chunk(c, h0, b, ct, smem_base + c * STAGEH * 2, barbase + c * 8);

    float d[4][8][4];
#pragma unroll
    for (int f = 0; f < 4; f++)
#pragma unroll
        for (int nf = 0; nf < 8; nf++)
#pragma unroll
            for (int k = 0; k < 4; k++) d[f][nf][k] = 0.0f;

    for (int c = 0; c < CKN; c++) {
        const int s = c % NSTAGE;
        const int r = c / NSTAGE;
        mbar_wait(barbase + s * 8, r & 1);
        const __half* xs = smem + s * STAGEH;
        const __half* ws = xs + XH;

#pragma unroll
        for (int tap = 0; tap < 5; tap++) {
            const int xrow  = row + ((tap == 0) ? 0 : (tap == 4 ? 2 : 1));
            const int shift = (tap == 1) ? -1 : ((tap == 3) ? 1 : 0);

            const __half* xb0 = xs + xrow * XROWH + tig * 4;
            uint32_t a[4][4];
#pragma unroll
            for (int f = 0; f < 4; f++) {
                const int sp = pbase + f * 16 + grp + shift + 1;  // padded index
                const uint2 lo = *(const uint2*)(xb0 + sp * 16);          // row grp
                const uint2 hi = *(const uint2*)(xb0 + (sp + 8) * 16);    // row grp+8
                a[f][0] = lo.x;   // (pix, k 2t..2t+1)
                a[f][1] = hi.x;   // (pix+8, k 2t..2t+1)
                a[f][2] = lo.y;   // (pix, k 2t+8..2t+9)
                a[f][3] = hi.y;   // (pix+8, k 2t+8..2t+9)
            }
            const __half* wb = ws + (tap * 128 + ng * 64 + grp) * 16 + tig * 4;
#pragma unroll
            for (int nf = 0; nf < 8; nf++) {
                const uint2 bv = *(const uint2*)(wb + nf * 128);
                mma16(d[0][nf], a[0], bv.x, bv.y);
                mma16(d[1][nf], a[1], bv.x, bv.y);
                mma16(d[2][nf], a[2], bv.x, bv.y);
                mma16(d[3][nf], a[3], bv.x, bv.y);
            }
        }
        if (lane == 0) mbar_arrive(barbase + NSTAGE * 8 + s * 8);
        if (tid == 0 && c + NSTAGE < CKN) {
            mbar_wait(barbase + NSTAGE * 8 + s * 8, r & 1);
            issue_chunk(c + NSTAGE, h0, b, ct, smem_base + s * STAGEH * 2, barbase + s * 8);
        }
    }

    // ---- epilogue: demod folded into weights -> pure store ----
    float* ob = out + (((size_t)b * CO + ct * 128) * HH + (h0 + row)) * WW;
#pragma unroll
    for (int f = 0; f < 4; f++) {
        const int p = pbase + f * 16 + grp;
#pragma unroll
        for (int nf = 0; nf < 8; nf++) {
            const int co = ng * 64 + nf * 8 + tig * 2;
            ob[(size_t)co * (HH * WW) + p]           = d[f][nf][0];
            ob[(size_t)(co + 1) * (HH * WW) + p]     = d[f][nf][1];
            ob[(size_t)co * (HH * WW) + p + 8]       = d[f][nf][2];
            ob[(size_t)(co + 1) * (HH * WW) + p + 8] = d[f][nf][3];
        }
    }
}

extern "C" void kernel_launch(void* const* d_in, const int* in_sizes, int n_in,
                              void* d_out, int out_size) {
    const float* x = (const float*)d_in[0];
    const float* y = (const float*)d_in[1];
    const float* w = (const float*)d_in[2];
    float* out = (float*)d_out;

    cudaFuncSetAttribute(conv_mma_kernel, cudaFuncAttributeMaxDynamicSharedMemorySize, SMEM_DYN);

    demod_kernel<<<dim3(CO, BS), 256>>>(y, w);
    prep_x_kernel<<<dim3(HH, CKN, BS), 256>>>(x);
    prep_w_kernel<<<dim3(CKN, 2, BS), 128>>>(w, y);
    conv_mma_kernel<<<dim3(HH / 2, 2, BS), 256, SMEM_DYN>>>(out);
}

// round 9
// speedup vs baseline: 1.0835x; 1.0835x over previous
#include <cuda_runtime.h>
#include <cuda_fp16.h>
#include <cstdint>
#include <cstddef>

#define BS 8
#define CI 256
#define CO 256
#define HH 128
#define WW 128
#define EPSV 1e-6f

#define CKN 16                    // ci chunks of 16
// Stage layout (halves):
//  X: [xrow 4][pix 130 padded][ci 16 plain] = 8320 halves (16640 B)
//  W: [tap 5][co 128][16 slots]             = 10240 halves (20480 B)
#define XROWH 2080
#define XH (4 * XROWH)            // 8320
#define WH 10240
#define STAGEH (XH + WH)          // 18560 halves = 37120 B
#define NSTAGE 4
#define TXBYTES (STAGEH * 2)
#define SMEM_DYN (NSTAGE * STAGEH * 2 + 256)

// ---------------- device scratch (no cudaMalloc allowed) ----------------
// x: fp16, padded, PLAIN k-order: block (b*16+ck)*128+h of 2080 halves: [pix 0..129][ci 16]
__device__ __align__(16) __half g_xt[(size_t)BS * CKN * HH * XROWH];
// w_eff = fp16(w * (1+y) * demod): block ((b*2+ct)*16+ck): [tap][co][slot 16]
// slot pairs p: p=2t -> ci(2t,2t+1), p=2t+1 -> ci(2t+8,2t+9)
__device__ __align__(16) __half g_weff[(size_t)BS * 2 * CKN * WH];
__device__ float g_demod[BS * CO];
__device__ __align__(16) __half g_zero[XROWH];   // zero halo row (.bss)

// ---------------- PTX helpers (base sm_103 legal; NO tcgen05) ----------------
__device__ __forceinline__ uint32_t smem_u32(const void* p) {
    uint32_t a;
    asm("{ .reg .u64 t; cvta.to.shared.u64 t, %1; cvt.u32.u64 %0, t; }" : "=r"(a) : "l"(p));
    return a;
}
__device__ __forceinline__ void mbar_init(uint32_t mbar, uint32_t cnt) {
    asm volatile("mbarrier.init.shared.b64 [%0], %1;" :: "r"(mbar), "r"(cnt) : "memory");
}
__device__ __forceinline__ void mbar_expect_tx(uint32_t mbar, uint32_t bytes) {
    asm volatile("mbarrier.arrive.expect_tx.shared.b64 _, [%0], %1;"
                 :: "r"(mbar), "r"(bytes) : "memory");
}
__device__ __forceinline__ void mbar_arrive(uint32_t mbar) {
    asm volatile("mbarrier.arrive.shared.b64 _, [%0];" :: "r"(mbar) : "memory");
}
__device__ __forceinline__ void mbar_wait(uint32_t mbar, uint32_t parity) {
    asm volatile(
        "{\n\t.reg .pred P;\n\t"
        "WL_%=:\n\t"
        "mbarrier.try_wait.parity.acquire.cta.shared::cta.b64 P, [%0], %1, 0x989680;\n\t"
        "@P bra.uni WD_%=;\n\t"
        "bra.uni WL_%=;\n\t"
        "WD_%=:\n\t}"
        :: "r"(mbar), "r"(parity) : "memory");
}
__device__ __forceinline__ void bulk_g2s(uint32_t dst, const void* src, uint32_t bytes, uint32_t mbar) {
    asm volatile(
        "cp.async.bulk.shared::cluster.global.mbarrier::complete_tx::bytes [%0], [%1], %2, [%3];"
        :: "r"(dst), "l"(src), "r"(bytes), "r"(mbar) : "memory");
}
__device__ __forceinline__ void fence_async() {
    asm volatile("fence.proxy.async.shared::cta;" ::: "memory");
}
// ldmatrix x4: A fragment for m16n8k16 (canonical tile order)
__device__ __forceinline__ void ldsm_x4(uint32_t* r, uint32_t addr) {
    asm volatile("ldmatrix.sync.aligned.m8n8.x4.shared.b16 {%0,%1,%2,%3}, [%4];"
                 : "=r"(r[0]), "=r"(r[1]), "=r"(r[2]), "=r"(r[3]) : "r"(addr));
}
// m16n8k16 fp16 MMA, fp32 accumulate
__device__ __forceinline__ void mma16(float* d, const uint32_t* a, uint32_t b0, uint32_t b1) {
    asm volatile(
        "mma.sync.aligned.m16n8k16.row.col.f32.f16.f16.f32 "
        "{%0,%1,%2,%3}, {%4,%5,%6,%7}, {%8,%9}, {%0,%1,%2,%3};"
        : "+f"(d[0]), "+f"(d[1]), "+f"(d[2]), "+f"(d[3])
        : "r"(a[0]), "r"(a[1]), "r"(a[2]), "r"(a[3]), "r"(b0), "r"(b1));
}

// ---------------- prologue: demod ----------------
__global__ void demod_kernel(const float* __restrict__ y, const float* __restrict__ w) {
    int o = blockIdx.x, b = blockIdx.y, ci = threadIdx.x;
    float m = 1.0f + y[b * CI + ci];
    const float* wr = w + ((size_t)o * CI + ci) * 5;
    float s = wr[0]*wr[0] + wr[1]*wr[1] + wr[2]*wr[2] + wr[3]*wr[3] + wr[4]*wr[4];
    float v = m * m * s;
#pragma unroll
    for (int off = 16; off; off >>= 1) v += __shfl_xor_sync(0xffffffffu, v, off);
    __shared__ float red[8];
    if ((threadIdx.x & 31) == 0) red[threadIdx.x >> 5] = v;
    __syncthreads();
    if (threadIdx.x == 0) {
        float t = red[0]+red[1]+red[2]+red[3]+red[4]+red[5]+red[6]+red[7];
        g_demod[b * CO + o] = rsqrtf(t + EPSV);
    }
}

// ---------------- prologue: x -> fp16, transpose, pad (PLAIN k order) ---------------
__global__ __launch_bounds__(256) void prep_x_kernel(const float* __restrict__ x) {
    __shared__ float xs[16][132];
    const int t = threadIdx.x;
    const int h = blockIdx.x, ck = blockIdx.y, b = blockIdx.z;

    const float* src = x + ((size_t)(b * CI + ck * 16) * HH + h) * WW;
#pragma unroll
    for (int r = 0; r < 8; r++) {
        int idx = t + r * 256;
        int j = idx >> 7, pix = idx & 127;
        xs[j][pix] = src[(size_t)j * HH * WW + pix];
    }
    __syncthreads();

    __half2* dst = (__half2*)(g_xt + ((size_t)((b * CKN + ck) * HH + h)) * XROWH);
#pragma unroll
    for (int r = 0; r < 4; r++) {
        int o = t + r * 256;               // 0..1023: pix*8 + cpair
        int pix = o >> 3, p = o & 7;
        int ci0 = p * 2;                   // plain order
        dst[(pix + 1) * 8 + p] = __floats2half2_rn(xs[ci0][pix], xs[ci0 + 1][pix]);
    }
    if (t < 16) {   // zero borders: pix 0 and 129
        int side = t >> 3, p = t & 7;
        dst[(side ? 129 : 0) * 8 + p] = __floats2half2_rn(0.f, 0.f);
    }
}

// ---------------- prologue: modulated+demodulated fp16 weights (slot layout) --------
__global__ __launch_bounds__(128) void prep_w_kernel(
    const float* __restrict__ w, const float* __restrict__ y)
{
    const int ck = blockIdx.x, ct = blockIdx.y, b = blockIdx.z;
    const int co = threadIdx.x;
    const int o = ct * 128 + co;
    const float dd = g_demod[b * CO + o];
    __half2* blk = (__half2*)(g_weff + ((size_t)((b * 2 + ct) * CKN + ck)) * WH);
#pragma unroll
    for (int p = 0; p < 8; p++) {
        const int j0 = ((p >> 1) << 1) + ((p & 1) << 3);
        const int ci0 = ck * 16 + j0;
        const float m0 = (1.0f + y[b * CI + ci0]) * dd;
        const float m1 = (1.0f + y[b * CI + ci0 + 1]) * dd;
        const float* wp0 = w + ((size_t)o * CI + ci0) * 5;
        const float* wp1 = wp0 + 5;
#pragma unroll
        for (int tap = 0; tap < 5; tap++)
            blk[(tap * 128 + co) * 8 + p] = __floats2half2_rn(wp0[tap] * m0, wp1[tap] * m1);
    }
}

// ---------------- producer: one chunk into a stage ----------------
__device__ __forceinline__ void issue_chunk(
    int c, int h0, int b, int ct, uint32_t stage_dst, uint32_t full_mb)
{
    mbar_expect_tx(full_mb, TXBYTES);
    const __half* xb = g_xt + ((size_t)(b * CKN + c) * HH) * XROWH;
    if (h0 >= 2 && h0 <= 124) {
        bulk_g2s(stage_dst, xb + (size_t)(h0 - 1) * XROWH, 4 * XROWH * 2, full_mb);
    } else if (h0 == 0) {
        bulk_g2s(stage_dst, g_zero, XROWH * 2, full_mb);
        bulk_g2s(stage_dst + XROWH * 2, xb, 3 * XROWH * 2, full_mb);
    } else { // h0 == 126
        bulk_g2s(stage_dst, xb + (size_t)125 * XROWH, 3 * XROWH * 2, full_mb);
        bulk_g2s(stage_dst + 3 * XROWH * 2, g_zero, XROWH * 2, full_mb);
    }
    bulk_g2s(stage_dst + XH * 2,
             g_weff + ((size_t)((b * 2 + ct) * CKN + c)) * WH, WH * 2, full_mb);
}

// ---- main: fp16 mma.sync, 16 compute warps (M64xN32) + 1 producer warp, 4 stages ----
__global__ __launch_bounds__(544, 1) void conv_mma_kernel(float* __restrict__ out) {
    extern __shared__ __half smem[];
    const uint32_t smem_base = smem_u32(smem);
    const uint32_t barbase = smem_base + NSTAGE * STAGEH * 2;

    const int tid  = threadIdx.x;
    const int lane = tid & 31;
    const int wid  = tid >> 5;
    const int grp  = lane >> 2;
    const int tig  = lane & 3;

    const int h0 = blockIdx.x * 2;
    const int ct = blockIdx.y;
    const int b  = blockIdx.z;

    if (tid == 0) {
        for (int s = 0; s < NSTAGE; s++) {
            mbar_init(barbase + s * 8, 1);                    // full
            mbar_init(barbase + NSTAGE * 8 + s * 8, 16);      // empty (per compute warp)
        }
        fence_async();
    }
    __syncthreads();

    if (wid == 16) {
        // ---------- dedicated producer warp ----------
        if (lane == 0) {
            for (int cc = 0; cc < CKN; cc++) {
                const int s = cc % NSTAGE;
                if (cc >= NSTAGE) {
                    const int r = (cc - NSTAGE) / NSTAGE;
                    mbar_wait(barbase + NSTAGE * 8 + s * 8, r & 1);
                }
                issue_chunk(cc, h0, b, ct, smem_base + s * STAGEH * 2, barbase + s * 8);
            }
        }
        return;
    }

    // ---------- compute warps ----------
    const int mg = wid >> 2;             // 0..3 : M64 tile over M=256
    const int ng = wid & 3;              // 0..3 : N32 tile over N=128
    const int row = mg >> 1;             // output row within CTA (0/1)
    const int pbase = (mg & 1) * 64;     // pixel base

    // per-lane invariant ldmatrix offset: rows = pix (lane&15), +16B for k8 half
    const uint32_t loff = (uint32_t)((lane & 15) * 32 + (lane >> 4) * 16);

    float d[4][4][4];
#pragma unroll
    for (int f = 0; f < 4; f++)
#pragma unroll
        for (int nf = 0; nf < 4; nf++)
#pragma unroll
            for (int k = 0; k < 4; k++) d[f][nf][k] = 0.0f;

    for (int c = 0; c < CKN; c++) {
        const int s = c % NSTAGE;
        const int r = c / NSTAGE;
        mbar_wait(barbase + s * 8, r & 1);
        const uint32_t xs_u = smem_base + s * STAGEH * 2 + loff;
        const __half* ws = smem + s * STAGEH + XH;

#pragma unroll
        for (int tap = 0; tap < 5; tap++) {
            const int xrow  = row + ((tap == 0) ? 0 : (tap == 4 ? 2 : 1));
            const int shift = (tap == 1) ? -1 : ((tap == 3) ? 1 : 0);
            // warp-uniform base for this tap (padded pix index)
            const uint32_t ub = xs_u + (uint32_t)(xrow * (XROWH * 2)
                              + (pbase + 1 + shift) * 32);
            uint32_t a[4][4];
#pragma unroll
            for (int f = 0; f < 4; f++)
                ldsm_x4(a[f], ub + (uint32_t)(f * 512));
            const __half* wb = ws + (tap * 128 + ng * 32 + grp) * 16 + tig * 4;
#pragma unroll
            for (int nf = 0; nf < 4; nf++) {
                const uint2 bv = *(const uint2*)(wb + nf * 128);
                mma16(d[0][nf], a[0], bv.x, bv.y);
                mma16(d[1][nf], a[1], bv.x, bv.y);
                mma16(d[2][nf], a[2], bv.x, bv.y);
                mma16(d[3][nf], a[3], bv.x, bv.y);
            }
        }
        if (lane == 0) mbar_arrive(barbase + NSTAGE * 8 + s * 8);
    }

    // ---- epilogue: demod folded into weights -> pure store ----
    float* ob = out + (((size_t)b * CO + ct * 128) * HH + (h0 + row)) * WW;
#pragma unroll
    for (int f = 0; f < 4; f++) {
        const int p = pbase + f * 16 + grp;
#pragma unroll
        for (int nf = 0; nf < 4; nf++) {
            const int co = ng * 32 + nf * 8 + tig * 2;
            ob[(size_t)co * (HH * WW) + p]           = d[f][nf][0];
            ob[(size_t)(co + 1) * (HH * WW) + p]     = d[f][nf][1];
            ob[(size_t)co * (HH * WW) + p + 8]       = d[f][nf][2];
            ob[(size_t)(co + 1) * (HH * WW) + p + 8] = d[f][nf][3];
        }
    }
}

extern "C" void kernel_launch(void* const* d_in, const int* in_sizes, int n_in,
                              void* d_out, int out_size) {
    const float* x = (const float*)d_in[0];
    const float* y = (const float*)d_in[1];
    const float* w = (const float*)d_in[2];
    float* out = (float*)d_out;

    cudaFuncSetAttribute(conv_mma_kernel, cudaFuncAttributeMaxDynamicSharedMemorySize, SMEM_DYN);

    demod_kernel<<<dim3(CO, BS), 256>>>(y, w);
    prep_x_kernel<<<dim3(HH, CKN, BS), 256>>>(x);
    prep_w_kernel<<<dim3(CKN, 2, BS), 128>>>(w, y);
    conv_mma_kernel<<<dim3(HH / 2, 2, BS), 544, SMEM_DYN>>>(out);
}

// round 10
// speedup vs baseline: 1.1479x; 1.0594x over previous
#include <cuda_runtime.h>
#include <cuda_fp16.h>
#include <cstdint>
#include <cstddef>

#define BS 8
#define CI 256
#define CO 256
#define HH 128
#define WW 128
#define EPSV 1e-6f

#define CKN 16                    // ci chunks of 16
// Stage layout (halves):
//  X: [xrow 4][chalf 2][pix 130][8 halves] = 8320 halves (16640 B)
//  W: [tap 5][co 128][16 slots]            = 10240 halves (20480 B)
#define XROWH 2080                // one xrow: 2 planes x 130 x 8
#define XPLANEB 2080              // one chalf plane in BYTES: 130*16
#define XH (4 * XROWH)            // 8320
#define WH 10240
#define STAGEH (XH + WH)          // 18560 halves = 37120 B
#define NSTAGE 4
#define TXBYTES (STAGEH * 2)
#define SMEM_DYN (NSTAGE * STAGEH * 2 + 256)

// ---------------- device scratch (no cudaMalloc allowed) ----------------
// x: fp16, padded: block (b*16+ck)*128+h of 2080 halves: [chalf 2][pix 0..129][8 halves]
__device__ __align__(16) __half g_xt[(size_t)BS * CKN * HH * XROWH];
// w_eff = fp16(w * (1+y) * demod): block ((b*2+ct)*16+ck): [tap][co][slot 16]
// slot pairs p: p=2t -> ci(2t,2t+1), p=2t+1 -> ci(2t+8,2t+9)
__device__ __align__(16) __half g_weff[(size_t)BS * 2 * CKN * WH];
__device__ float g_demod[BS * CO];
__device__ __align__(16) __half g_zero[XROWH];   // zero halo row (.bss)

// ---------------- PTX helpers (base sm_103 legal; NO tcgen05) ----------------
__device__ __forceinline__ uint32_t smem_u32(const void* p) {
    uint32_t a;
    asm("{ .reg .u64 t; cvta.to.shared.u64 t, %1; cvt.u32.u64 %0, t; }" : "=r"(a) : "l"(p));
    return a;
}
__device__ __forceinline__ void mbar_init(uint32_t mbar, uint32_t cnt) {
    asm volatile("mbarrier.init.shared.b64 [%0], %1;" :: "r"(mbar), "r"(cnt) : "memory");
}
__device__ __forceinline__ void mbar_expect_tx(uint32_t mbar, uint32_t bytes) {
    asm volatile("mbarrier.arrive.expect_tx.shared.b64 _, [%0], %1;"
                 :: "r"(mbar), "r"(bytes) : "memory");
}
__device__ __forceinline__ void mbar_arrive(uint32_t mbar) {
    asm volatile("mbarrier.arrive.shared.b64 _, [%0];" :: "r"(mbar) : "memory");
}
__device__ __forceinline__ void mbar_wait(uint32_t mbar, uint32_t parity) {
    asm volatile(
        "{\n\t.reg .pred P;\n\t"
        "WL_%=:\n\t"
        "mbarrier.try_wait.parity.acquire.cta.shared::cta.b64 P, [%0], %1, 0x989680;\n\t"
        "@P bra.uni WD_%=;\n\t"
        "bra.uni WL_%=;\n\t"
        "WD_%=:\n\t}"
        :: "r"(mbar), "r"(parity) : "memory");
}
__device__ __forceinline__ void bulk_g2s(uint32_t dst, const void* src, uint32_t bytes, uint32_t mbar) {
    asm volatile(
        "cp.async.bulk.shared::cluster.global.mbarrier::complete_tx::bytes [%0], [%1], %2, [%3];"
        :: "r"(dst), "l"(src), "r"(bytes), "r"(mbar) : "memory");
}
__device__ __forceinline__ void fence_async() {
    asm volatile("fence.proxy.async.shared::cta;" ::: "memory");
}
// ldmatrix x4: A fragment for m16n8k16 (canonical tile order)
__device__ __forceinline__ void ldsm_x4(uint32_t* r, uint32_t addr) {
    asm volatile("ldmatrix.sync.aligned.m8n8.x4.shared.b16 {%0,%1,%2,%3}, [%4];"
                 : "=r"(r[0]), "=r"(r[1]), "=r"(r[2]), "=r"(r[3]) : "r"(addr));
}
// m16n8k16 fp16 MMA, fp32 accumulate
__device__ __forceinline__ void mma16(float* d, const uint32_t* a, uint32_t b0, uint32_t b1) {
    asm volatile(
        "mma.sync.aligned.m16n8k16.row.col.f32.f16.f16.f32 "
        "{%0,%1,%2,%3}, {%4,%5,%6,%7}, {%8,%9}, {%0,%1,%2,%3};"
        : "+f"(d[0]), "+f"(d[1]), "+f"(d[2]), "+f"(d[3])
        : "r"(a[0]), "r"(a[1]), "r"(a[2]), "r"(a[3]), "r"(b0), "r"(b1));
}

// ---------------- prologue: demod ----------------
__global__ void demod_kernel(const float* __restrict__ y, const float* __restrict__ w) {
    int o = blockIdx.x, b = blockIdx.y, ci = threadIdx.x;
    float m = 1.0f + y[b * CI + ci];
    const float* wr = w + ((size_t)o * CI + ci) * 5;
    float s = wr[0]*wr[0] + wr[1]*wr[1] + wr[2]*wr[2] + wr[3]*wr[3] + wr[4]*wr[4];
    float v = m * m * s;
#pragma unroll
    for (int off = 16; off; off >>= 1) v += __shfl_xor_sync(0xffffffffu, v, off);
    __shared__ float red[8];
    if ((threadIdx.x & 31) == 0) red[threadIdx.x >> 5] = v;
    __syncthreads();
    if (threadIdx.x == 0) {
        float t = red[0]+red[1]+red[2]+red[3]+red[4]+red[5]+red[6]+red[7];
        g_demod[b * CO + o] = rsqrtf(t + EPSV);
    }
}

// ---------------- prologue: x -> fp16, transpose, pad, k-half planes ----------------
__global__ __launch_bounds__(256) void prep_x_kernel(const float* __restrict__ x) {
    __shared__ float xs[16][132];
    const int t = threadIdx.x;
    const int h = blockIdx.x, ck = blockIdx.y, b = blockIdx.z;

    const float* src = x + ((size_t)(b * CI + ck * 16) * HH + h) * WW;
#pragma unroll
    for (int r = 0; r < 8; r++) {
        int idx = t + r * 256;
        int j = idx >> 7, pix = idx & 127;
        xs[j][pix] = src[(size_t)j * HH * WW + pix];
    }
    __syncthreads();

    __half2* dst = (__half2*)(g_xt + ((size_t)((b * CKN + ck) * HH + h)) * XROWH);
#pragma unroll
    for (int r = 0; r < 4; r++) {
        int o = t + r * 256;               // 0..1023: pix*8 + cpair p
        int pix = o >> 3, p = o & 7;
        int ci0 = p * 2;                   // plain k order
        int chalf = p >> 2, q = p & 3;
        dst[chalf * 520 + (pix + 1) * 4 + q] = __floats2half2_rn(xs[ci0][pix], xs[ci0 + 1][pix]);
    }
    if (t < 16) {   // zero borders: pix 0 and 129, both planes
        int side = t >> 3, p = t & 7;
        int chalf = p >> 2, q = p & 3;
        dst[chalf * 520 + (side ? 129 : 0) * 4 + q] = __floats2half2_rn(0.f, 0.f);
    }
}

// ---------------- prologue: modulated+demodulated fp16 weights (slot layout) --------
__global__ __launch_bounds__(128) void prep_w_kernel(
    const float* __restrict__ w, const float* __restrict__ y)
{
    const int ck = blockIdx.x, ct = blockIdx.y, b = blockIdx.z;
    const int co = threadIdx.x;
    const int o = ct * 128 + co;
    const float dd = g_demod[b * CO + o];
    __half2* blk = (__half2*)(g_weff + ((size_t)((b * 2 + ct) * CKN + ck)) * WH);
#pragma unroll
    for (int p = 0; p < 8; p++) {
        const int j0 = ((p >> 1) << 1) + ((p & 1) << 3);
        const int ci0 = ck * 16 + j0;
        const float m0 = (1.0f + y[b * CI + ci0]) * dd;
        const float m1 = (1.0f + y[b * CI + ci0 + 1]) * dd;
        const float* wp0 = w + ((size_t)o * CI + ci0) * 5;
        const float* wp1 = wp0 + 5;
#pragma unroll
        for (int tap = 0; tap < 5; tap++)
            blk[(tap * 128 + co) * 8 + p] = __floats2half2_rn(wp0[tap] * m0, wp1[tap] * m1);
    }
}

// ---------------- producer: one chunk into a stage ----------------
__device__ __forceinline__ void issue_chunk(
    int c, int h0, int b, int ct, uint32_t stage_dst, uint32_t full_mb)
{
    mbar_expect_tx(full_mb, TXBYTES);
    const __half* xb = g_xt + ((size_t)(b * CKN + c) * HH) * XROWH;
    if (h0 >= 2 && h0 <= 124) {
        bulk_g2s(stage_dst, xb + (size_t)(h0 - 1) * XROWH, 4 * XROWH * 2, full_mb);
    } else if (h0 == 0) {
        bulk_g2s(stage_dst, g_zero, XROWH * 2, full_mb);
        bulk_g2s(stage_dst + XROWH * 2, xb, 3 * XROWH * 2, full_mb);
    } else { // h0 == 126
        bulk_g2s(stage_dst, xb + (size_t)125 * XROWH, 3 * XROWH * 2, full_mb);
        bulk_g2s(stage_dst + 3 * XROWH * 2, g_zero, XROWH * 2, full_mb);
    }
    bulk_g2s(stage_dst + XH * 2,
             g_weff + ((size_t)((b * 2 + ct) * CKN + c)) * WH, WH * 2, full_mb);
}

// ---- main: fp16 mma.sync, 8 compute warps (M64xN64) + 1 producer warp, 4 stages ----
__global__ __launch_bounds__(288, 1) void conv_mma_kernel(float* __restrict__ out) {
    extern __shared__ __half smem[];
    const uint32_t smem_base = smem_u32(smem);
    const uint32_t barbase = smem_base + NSTAGE * STAGEH * 2;

    const int tid  = threadIdx.x;
    const int lane = tid & 31;
    const int wid  = tid >> 5;
    const int grp  = lane >> 2;
    const int tig  = lane & 3;

    const int h0 = blockIdx.x * 2;
    const int ct = blockIdx.y;
    const int b  = blockIdx.z;

    if (tid == 0) {
        for (int s = 0; s < NSTAGE; s++) {
            mbar_init(barbase + s * 8, 1);                   // full
            mbar_init(barbase + NSTAGE * 8 + s * 8, 8);      // empty (per compute warp)
        }
        fence_async();
    }
    __syncthreads();

    if (wid == 8) {
        // ---------- dedicated producer warp ----------
        if (lane == 0) {
            for (int cc = 0; cc < CKN; cc++) {
                const int s = cc % NSTAGE;
                if (cc >= NSTAGE) {
                    const int r = (cc - NSTAGE) / NSTAGE;
                    mbar_wait(barbase + NSTAGE * 8 + s * 8, r & 1);
                }
                issue_chunk(cc, h0, b, ct, smem_base + s * STAGEH * 2, barbase + s * 8);
            }
        }
        return;
    }

    // ---------- compute warps: M64 x N64 ----------
    const int mg = wid >> 1;             // 0..3 : M64 tile over M=256
    const int ng = wid & 1;              // 0..1 : N64 tile over N=128
    const int row = mg >> 1;             // output row within CTA (0/1)
    const int pbase = (mg & 1) * 64;     // pixel base

    // ldmatrix lane offset: lanes 0-15 -> pixels (k-half 0), 16-31 -> k-half 1 plane
    const uint32_t loff = (uint32_t)((lane & 15) * 16 + (lane >> 4) * XPLANEB);

    float d[4][8][4];
#pragma unroll
    for (int f = 0; f < 4; f++)
#pragma unroll
        for (int nf = 0; nf < 8; nf++)
#pragma unroll
            for (int k = 0; k < 4; k++) d[f][nf][k] = 0.0f;

    for (int c = 0; c < CKN; c++) {
        const int s = c % NSTAGE;
        const int r = c / NSTAGE;
        mbar_wait(barbase + s * 8, r & 1);
        const uint32_t xs_u = smem_base + s * STAGEH * 2 + loff;
        const __half* ws = smem + s * STAGEH + XH;

#pragma unroll
        for (int tap = 0; tap < 5; tap++) {
            const int xrow  = row + ((tap == 0) ? 0 : (tap == 4 ? 2 : 1));
            const int shift = (tap == 1) ? -1 : ((tap == 3) ? 1 : 0);
            // warp-uniform base for this tap (padded pix index, 16 B per pixel)
            const uint32_t ub = xs_u + (uint32_t)(xrow * (XROWH * 2)
                              + (pbase + 1 + shift) * 16);
            uint32_t a[4][4];
#pragma unroll
            for (int f = 0; f < 4; f++)
                ldsm_x4(a[f], ub + (uint32_t)(f * 256));
            const __half* wb = ws + (tap * 128 + ng * 64 + grp) * 16 + tig * 4;
#pragma unroll
            for (int nf = 0; nf < 8; nf++) {
                const uint2 bv = *(const uint2*)(wb + nf * 128);
                mma16(d[0][nf], a[0], bv.x, bv.y);
                mma16(d[1][nf], a[1], bv.x, bv.y);
                mma16(d[2][nf], a[2], bv.x, bv.y);
                mma16(d[3][nf], a[3], bv.x, bv.y);
            }
        }
        if (lane == 0) mbar_arrive(barbase + NSTAGE * 8 + s * 8);
    }

    // ---- epilogue: demod folded into weights -> pure store ----
    float* ob = out + (((size_t)b * CO + ct * 128) * HH + (h0 + row)) * WW;
#pragma unroll
    for (int f = 0; f < 4; f++) {
        const int p = pbase + f * 16 + grp;
#pragma unroll
        for (int nf = 0; nf < 8; nf++) {
            const int co = ng * 64 + nf * 8 + tig * 2;
            ob[(size_t)co * (HH * WW) + p]           = d[f][nf][0];
            ob[(size_t)(co + 1) * (HH * WW) + p]     = d[f][nf][1];
            ob[(size_t)co * (HH * WW) + p + 8]       = d[f][nf][2];
            ob[(size_t)(co + 1) * (HH * WW) + p + 8] = d[f][nf][3];
        }
    }
}

extern "C" void kernel_launch(void* const* d_in, const int* in_sizes, int n_in,
                              void* d_out, int out_size) {
    const float* x = (const float*)d_in[0];
    const float* y = (const float*)d_in[1];
    const float* w = (const float*)d_in[2];
    float* out = (float*)d_out;

    cudaFuncSetAttribute(conv_mma_kernel, cudaFuncAttributeMaxDynamicSharedMemorySize, SMEM_DYN);

    demod_kernel<<<dim3(CO, BS), 256>>>(y, w);
    prep_x_kernel<<<dim3(HH, CKN, BS), 256>>>(x);
    prep_w_kernel<<<dim3(CKN, 2, BS), 128>>>(w, y);
    conv_mma_kernel<<<dim3(HH / 2, 2, BS), 288, SMEM_DYN>>>(out);
}

// round 11
// speedup vs baseline: 1.1574x; 1.0083x over previous
#include <cuda_runtime.h>
#include <cuda_fp16.h>
#include <cstdint>
#include <cstddef>

#define BS 8
#define CI 256
#define CO 256
#define HH 128
#define WW 128
#define EPSV 1e-6f

#define CKN 16                    // ci chunks of 16
// Stage layout (halves):
//  X: [xrow 4][chalf 2][pix 130][8 halves] = 8320 halves (16640 B)
//  W: [tap 5][co 128][16 slots]            = 10240 halves (20480 B)
#define XROWH 2080                // one xrow: 2 planes x 130 x 8
#define XPLANEB 2080              // one chalf plane in BYTES: 130*16
#define XH (4 * XROWH)            // 8320
#define WH 10240
#define STAGEH (XH + WH)          // 18560 halves = 37120 B
#define NSTAGE 5
#define TXBYTES (STAGEH * 2)
#define SMEM_DYN (NSTAGE * STAGEH * 2 + 256)

// ---------------- device scratch (no cudaMalloc allowed) ----------------
// x: fp16, padded: block (b*16+ck)*128+h of 2080 halves: [chalf 2][pix 0..129][8 halves]
__device__ __align__(16) __half g_xt[(size_t)BS * CKN * HH * XROWH];
// w_eff = fp16(w * (1+y) * demod): block ((b*2+ct)*16+ck): [tap][co][slot 16]
// slot pairs p: p=2t -> ci(2t,2t+1), p=2t+1 -> ci(2t+8,2t+9)
__device__ __align__(16) __half g_weff[(size_t)BS * 2 * CKN * WH];
__device__ float g_demod[BS * CO];
__device__ __align__(16) __half g_zero[XROWH];   // zero halo row (.bss)

// ---------------- PTX helpers (base sm_103 legal; NO tcgen05) ----------------
__device__ __forceinline__ uint32_t smem_u32(const void* p) {
    uint32_t a;
    asm("{ .reg .u64 t; cvta.to.shared.u64 t, %1; cvt.u32.u64 %0, t; }" : "=r"(a) : "l"(p));
    return a;
}
__device__ __forceinline__ void mbar_init(uint32_t mbar, uint32_t cnt) {
    asm volatile("mbarrier.init.shared.b64 [%0], %1;" :: "r"(mbar), "r"(cnt) : "memory");
}
__device__ __forceinline__ void mbar_expect_tx(uint32_t mbar, uint32_t bytes) {
    asm volatile("mbarrier.arrive.expect_tx.shared.b64 _, [%0], %1;"
                 :: "r"(mbar), "r"(bytes) : "memory");
}
__device__ __forceinline__ void mbar_arrive(uint32_t mbar) {
    asm volatile("mbarrier.arrive.shared.b64 _, [%0];" :: "r"(mbar) : "memory");
}
__device__ __forceinline__ void mbar_wait(uint32_t mbar, uint32_t parity) {
    asm volatile(
        "{\n\t.reg .pred P;\n\t"
        "WL_%=:\n\t"
        "mbarrier.try_wait.parity.acquire.cta.shared::cta.b64 P, [%0], %1, 0x989680;\n\t"
        "@P bra.uni WD_%=;\n\t"
        "bra.uni WL_%=;\n\t"
        "WD_%=:\n\t}"
        :: "r"(mbar), "r"(parity) : "memory");
}
__device__ __forceinline__ void bulk_g2s(uint32_t dst, const void* src, uint32_t bytes, uint32_t mbar) {
    asm volatile(
        "cp.async.bulk.shared::cluster.global.mbarrier::complete_tx::bytes [%0], [%1], %2, [%3];"
        :: "r"(dst), "l"(src), "r"(bytes), "r"(mbar) : "memory");
}
__device__ __forceinline__ void fence_async() {
    asm volatile("fence.proxy.async.shared::cta;" ::: "memory");
}
// ldmatrix x4: A fragment for m16n8k16 (canonical tile order)
__device__ __forceinline__ void ldsm_x4(uint32_t* r, uint32_t addr) {
    asm volatile("ldmatrix.sync.aligned.m8n8.x4.shared.b16 {%0,%1,%2,%3}, [%4];"
                 : "=r"(r[0]), "=r"(r[1]), "=r"(r[2]), "=r"(r[3]) : "r"(addr));
}
// m16n8k16 fp16 MMA, fp32 accumulate
__device__ __forceinline__ void mma16(float* d, const uint32_t* a, uint32_t b0, uint32_t b1) {
    asm volatile(
        "mma.sync.aligned.m16n8k16.row.col.f32.f16.f16.f32 "
        "{%0,%1,%2,%3}, {%4,%5,%6,%7}, {%8,%9}, {%0,%1,%2,%3};"
        : "+f"(d[0]), "+f"(d[1]), "+f"(d[2]), "+f"(d[3])
        : "r"(a[0]), "r"(a[1]), "r"(a[2]), "r"(a[3]), "r"(b0), "r"(b1));
}

// ---------------- prologue: demod ----------------
__global__ void demod_kernel(const float* __restrict__ y, const float* __restrict__ w) {
    int o = blockIdx.x, b = blockIdx.y, ci = threadIdx.x;
    float m = 1.0f + y[b * CI + ci];
    const float* wr = w + ((size_t)o * CI + ci) * 5;
    float s = wr[0]*wr[0] + wr[1]*wr[1] + wr[2]*wr[2] + wr[3]*wr[3] + wr[4]*wr[4];
    float v = m * m * s;
#pragma unroll
    for (int off = 16; off; off >>= 1) v += __shfl_xor_sync(0xffffffffu, v, off);
    __shared__ float red[8];
    if ((threadIdx.x & 31) == 0) red[threadIdx.x >> 5] = v;
    __syncthreads();
    if (threadIdx.x == 0) {
        float t = red[0]+red[1]+red[2]+red[3]+red[4]+red[5]+red[6]+red[7];
        g_demod[b * CO + o] = rsqrtf(t + EPSV);
    }
}

// ---------------- prologue: x -> fp16, transpose, pad, k-half planes ----------------
__global__ __launch_bounds__(256) void prep_x_kernel(const float* __restrict__ x) {
    __shared__ float xs[16][132];
    const int t = threadIdx.x;
    const int h = blockIdx.x, ck = blockIdx.y, b = blockIdx.z;

    const float* src = x + ((size_t)(b * CI + ck * 16) * HH + h) * WW;
#pragma unroll
    for (int r = 0; r < 8; r++) {
        int idx = t + r * 256;
        int j = idx >> 7, pix = idx & 127;
        xs[j][pix] = src[(size_t)j * HH * WW + pix];
    }
    __syncthreads();

    __half2* dst = (__half2*)(g_xt + ((size_t)((b * CKN + ck) * HH + h)) * XROWH);
#pragma unroll
    for (int r = 0; r < 4; r++) {
        int o = t + r * 256;               // 0..1023: pix*8 + cpair p
        int pix = o >> 3, p = o & 7;
        int ci0 = p * 2;                   // plain k order
        int chalf = p >> 2, q = p & 3;
        dst[chalf * 520 + (pix + 1) * 4 + q] = __floats2half2_rn(xs[ci0][pix], xs[ci0 + 1][pix]);
    }
    if (t < 16) {   // zero borders: pix 0 and 129, both planes
        int side = t >> 3, p = t & 7;
        int chalf = p >> 2, q = p & 3;
        dst[chalf * 520 + (side ? 129 : 0) * 4 + q] = __floats2half2_rn(0.f, 0.f);
    }
}

// ---------------- prologue: modulated+demodulated fp16 weights (slot layout) --------
__global__ __launch_bounds__(128) void prep_w_kernel(
    const float* __restrict__ w, const float* __restrict__ y)
{
    const int ck = blockIdx.x, ct = blockIdx.y, b = blockIdx.z;
    const int co = threadIdx.x;
    const int o = ct * 128 + co;
    const float dd = g_demod[b * CO + o];
    __half2* blk = (__half2*)(g_weff + ((size_t)((b * 2 + ct) * CKN + ck)) * WH);
#pragma unroll
    for (int p = 0; p < 8; p++) {
        const int j0 = ((p >> 1) << 1) + ((p & 1) << 3);
        const int ci0 = ck * 16 + j0;
        const float m0 = (1.0f + y[b * CI + ci0]) * dd;
        const float m1 = (1.0f + y[b * CI + ci0 + 1]) * dd;
        const float* wp0 = w + ((size_t)o * CI + ci0) * 5;
        const float* wp1 = wp0 + 5;
#pragma unroll
        for (int tap = 0; tap < 5; tap++)
            blk[(tap * 128 + co) * 8 + p] = __floats2half2_rn(wp0[tap] * m0, wp1[tap] * m1);
    }
}

// ---------------- producer: one chunk into a stage ----------------
__device__ __forceinline__ void issue_chunk(
    int c, int h0, int b, int ct, uint32_t stage_dst, uint32_t full_mb)
{
    mbar_expect_tx(full_mb, TXBYTES);
    const __half* xb = g_xt + ((size_t)(b * CKN + c) * HH) * XROWH;
    if (h0 >= 2 && h0 <= 124) {
        bulk_g2s(stage_dst, xb + (size_t)(h0 - 1) * XROWH, 4 * XROWH * 2, full_mb);
    } else if (h0 == 0) {
        bulk_g2s(stage_dst, g_zero, XROWH * 2, full_mb);
        bulk_g2s(stage_dst + XROWH * 2, xb, 3 * XROWH * 2, full_mb);
    } else { // h0 == 126
        bulk_g2s(stage_dst, xb + (size_t)125 * XROWH, 3 * XROWH * 2, full_mb);
        bulk_g2s(stage_dst + 3 * XROWH * 2, g_zero, XROWH * 2, full_mb);
    }
    bulk_g2s(stage_dst + XH * 2,
             g_weff + ((size_t)((b * 2 + ct) * CKN + c)) * WH, WH * 2, full_mb);
}

// -- main: fp16 mma.sync, 16 compute warps (M64xN32) + 1 producer warp, 5 stages ------
__global__ __launch_bounds__(544, 1) void conv_mma_kernel(float* __restrict__ out) {
    extern __shared__ __half smem[];
    const uint32_t smem_base = smem_u32(smem);
    const uint32_t barbase = smem_base + NSTAGE * STAGEH * 2;

    const int tid  = threadIdx.x;
    const int lane = tid & 31;
    const int wid  = tid >> 5;
    const int grp  = lane >> 2;
    const int tig  = lane & 3;

    const int h0 = blockIdx.x * 2;
    const int ct = blockIdx.y;
    const int b  = blockIdx.z;

    if (tid == 0) {
        for (int s = 0; s < NSTAGE; s++) {
            mbar_init(barbase + s * 8, 1);                    // full
            mbar_init(barbase + NSTAGE * 8 + s * 8, 16);      // empty (per compute warp)
        }
        fence_async();
    }
    __syncthreads();

    if (wid == 16) {
        // ---------- dedicated producer warp ----------
        if (lane == 0) {
            for (int cc = 0; cc < CKN; cc++) {
                const int s = cc % NSTAGE;
                if (cc >= NSTAGE) {
                    const int r = (cc - NSTAGE) / NSTAGE;
                    mbar_wait(barbase + NSTAGE * 8 + s * 8, r & 1);
                }
                issue_chunk(cc, h0, b, ct, smem_base + s * STAGEH * 2, barbase + s * 8);
            }
        }
        return;
    }

    // ---------- compute warps: M64 x N32 ----------
    const int mg = wid >> 2;             // 0..3 : M64 tile over M=256
    const int ng = wid & 3;              // 0..3 : N32 tile over N=128
    const int row = mg >> 1;             // output row within CTA (0/1)
    const int pbase = (mg & 1) * 64;     // pixel base

    // ldmatrix lane offset: lanes 0-15 -> pixels (k-half 0), 16-31 -> k-half 1 plane
    const uint32_t loff = (uint32_t)((lane & 15) * 16 + (lane >> 4) * XPLANEB);

    float d[4][4][4];
#pragma unroll
    for (int f = 0; f < 4; f++)
#pragma unroll
        for (int nf = 0; nf < 4; nf++)
#pragma unroll
            for (int k = 0; k < 4; k++) d[f][nf][k] = 0.0f;

    for (int c = 0; c < CKN; c++) {
        const int s = c % NSTAGE;
        const int r = c / NSTAGE;
        mbar_wait(barbase + s * 8, r & 1);
        const uint32_t xs_u = smem_base + s * STAGEH * 2 + loff;
        const __half* ws = smem + s * STAGEH + XH;

#pragma unroll
        for (int tap = 0; tap < 5; tap++) {
            const int xrow  = row + ((tap == 0) ? 0 : (tap == 4 ? 2 : 1));
            const int shift = (tap == 1) ? -1 : ((tap == 3) ? 1 : 0);
            // warp-uniform base for this tap (padded pix index, 16 B per pixel)
            const uint32_t ub = xs_u + (uint32_t)(xrow * (XROWH * 2)
                              + (pbase + 1 + shift) * 16);
            uint32_t a[4][4];
#pragma unroll
            for (int f = 0; f < 4; f++)
                ldsm_x4(a[f], ub + (uint32_t)(f * 256));
            const __half* wb = ws + (tap * 128 + ng * 32 + grp) * 16 + tig * 4;
#pragma unroll
            for (int nf = 0; nf < 4; nf++) {
                const uint2 bv = *(const uint2*)(wb + nf * 128);
                mma16(d[0][nf], a[0], bv.x, bv.y);
                mma16(d[1][nf], a[1], bv.x, bv.y);
                mma16(d[2][nf], a[2], bv.x, bv.y);
                mma16(d[3][nf], a[3], bv.x, bv.y);
            }
        }
        if (lane == 0) mbar_arrive(barbase + NSTAGE * 8 + s * 8);
    }

    // ---- epilogue: demod folded into weights -> pure store ----
    float* ob = out + (((size_t)b * CO + ct * 128) * HH + (h0 + row)) * WW;
#pragma unroll
    for (int f = 0; f < 4; f++) {
        const int p = pbase + f * 16 + grp;
#pragma unroll
        for (int nf = 0; nf < 4; nf++) {
            const int co = ng * 32 + nf * 8 + tig * 2;
            ob[(size_t)co * (HH * WW) + p]           = d[f][nf][0];
            ob[(size_t)(co + 1) * (HH * WW) + p]     = d[f][nf][1];
            ob[(size_t)co * (HH * WW) + p + 8]       = d[f][nf][2];
            ob[(size_t)(co + 1) * (HH * WW) + p + 8] = d[f][nf][3];
        }
    }
}

extern "C" void kernel_launch(void* const* d_in, const int* in_sizes, int n_in,
                              void* d_out, int out_size) {
    const float* x = (const float*)d_in[0];
    const float* y = (const float*)d_in[1];
    const float* w = (const float*)d_in[2];
    float* out = (float*)d_out;

    cudaFuncSetAttribute(conv_mma_kernel, cudaFuncAttributeMaxDynamicSharedMemorySize, SMEM_DYN);

    demod_kernel<<<dim3(CO, BS), 256>>>(y, w);
    prep_x_kernel<<<dim3(HH, CKN, BS), 256>>>(x);
    prep_w_kernel<<<dim3(CKN, 2, BS), 128>>>(w, y);
    conv_mma_kernel<<<dim3(HH / 2, 2, BS), 544, SMEM_DYN>>>(out);
}

// round 12
// speedup vs baseline: 1.1648x; 1.0064x over previous
#include <cuda_runtime.h>
#include <cuda_fp16.h>
#include <cstdint>
#include <cstddef>

#define BS 8
#define CI 256
#define CO 256
#define HH 128
#define WW 128
#define EPSV 1e-6f

#define CKN 16                    // ci chunks of 16
// Stage layout (halves):
//  X: [xrow 4][chalf 2][pix 130][8 halves] = 8320 halves (16640 B)
//  W: [tap 5][co 128][16 slots]            = 10240 halves (20480 B)
#define XROWH 2080                // one xrow: 2 planes x 130 x 8
#define XPLANEB 2080              // one chalf plane in BYTES: 130*16
#define XH (4 * XROWH)            // 8320
#define WH 10240
#define STAGEH (XH + WH)          // 18560 halves = 37120 B
#define NSTAGE 5
#define TXBYTES (STAGEH * 2)
#define SMEM_DYN (NSTAGE * STAGEH * 2 + 256)

// ---------------- device scratch (no cudaMalloc allowed) ----------------
// x: fp16, padded: block (b*16+ck)*128+h of 2080 halves: [chalf 2][pix 0..129][8 halves]
__device__ __align__(16) __half g_xt[(size_t)BS * CKN * HH * XROWH];
// w_eff = fp16(w * (1+y) * demod): block ((b*2+ct)*16+ck): [tap][co][slot 16]
// slot pairs p: p=2t -> ci(2t,2t+1), p=2t+1 -> ci(2t+8,2t+9)
__device__ __align__(16) __half g_weff[(size_t)BS * 2 * CKN * WH];
__device__ float g_demod[BS * CO];
__device__ __align__(16) __half g_zero[XROWH];   // zero halo row (.bss)

// ---------------- PTX helpers (base sm_103 legal; NO tcgen05) ----------------
__device__ __forceinline__ uint32_t smem_u32(const void* p) {
    uint32_t a;
    asm("{ .reg .u64 t; cvta.to.shared.u64 t, %1; cvt.u32.u64 %0, t; }" : "=r"(a) : "l"(p));
    return a;
}
__device__ __forceinline__ void mbar_init(uint32_t mbar, uint32_t cnt) {
    asm volatile("mbarrier.init.shared.b64 [%0], %1;" :: "r"(mbar), "r"(cnt) : "memory");
}
__device__ __forceinline__ void mbar_expect_tx(uint32_t mbar, uint32_t bytes) {
    asm volatile("mbarrier.arrive.expect_tx.shared.b64 _, [%0], %1;"
                 :: "r"(mbar), "r"(bytes) : "memory");
}
__device__ __forceinline__ void mbar_arrive(uint32_t mbar) {
    asm volatile("mbarrier.arrive.shared.b64 _, [%0];" :: "r"(mbar) : "memory");
}
__device__ __forceinline__ void mbar_wait(uint32_t mbar, uint32_t parity) {
    asm volatile(
        "{\n\t.reg .pred P;\n\t"
        "WL_%=:\n\t"
        "mbarrier.try_wait.parity.acquire.cta.shared::cta.b64 P, [%0], %1, 0x989680;\n\t"
        "@P bra.uni WD_%=;\n\t"
        "bra.uni WL_%=;\n\t"
        "WD_%=:\n\t}"
        :: "r"(mbar), "r"(parity) : "memory");
}
__device__ __forceinline__ void bulk_g2s(uint32_t dst, const void* src, uint32_t bytes, uint32_t mbar) {
    asm volatile(
        "cp.async.bulk.shared::cluster.global.mbarrier::complete_tx::bytes [%0], [%1], %2, [%3];"
        :: "r"(dst), "l"(src), "r"(bytes), "r"(mbar) : "memory");
}
__device__ __forceinline__ void fence_async() {
    asm volatile("fence.proxy.async.shared::cta;" ::: "memory");
}
// ldmatrix x4: A fragment for m16n8k16 (canonical tile order)
__device__ __forceinline__ void ldsm_x4(uint32_t* r, uint32_t addr) {
    asm volatile("ldmatrix.sync.aligned.m8n8.x4.shared.b16 {%0,%1,%2,%3}, [%4];"
                 : "=r"(r[0]), "=r"(r[1]), "=r"(r[2]), "=r"(r[3]) : "r"(addr));
}
// m16n8k16 fp16 MMA, fp32 accumulate
__device__ __forceinline__ void mma16(float* d, const uint32_t* a, uint32_t b0, uint32_t b1) {
    asm volatile(
        "mma.sync.aligned.m16n8k16.row.col.f32.f16.f16.f32 "
        "{%0,%1,%2,%3}, {%4,%5,%6,%7}, {%8,%9}, {%0,%1,%2,%3};"
        : "+f"(d[0]), "+f"(d[1]), "+f"(d[2]), "+f"(d[3])
        : "r"(a[0]), "r"(a[1]), "r"(a[2]), "r"(a[3]), "r"(b0), "r"(b1));
}

// ---------------- prologue: demod ----------------
__global__ void demod_kernel(const float* __restrict__ y, const float* __restrict__ w) {
    int o = blockIdx.x, b = blockIdx.y, ci = threadIdx.x;
    float m = 1.0f + y[b * CI + ci];
    const float* wr = w + ((size_t)o * CI + ci) * 5;
    float s = wr[0]*wr[0] + wr[1]*wr[1] + wr[2]*wr[2] + wr[3]*wr[3] + wr[4]*wr[4];
    float v = m * m * s;
#pragma unroll
    for (int off = 16; off; off >>= 1) v += __shfl_xor_sync(0xffffffffu, v, off);
    __shared__ float red[8];
    if ((threadIdx.x & 31) == 0) red[threadIdx.x >> 5] = v;
    __syncthreads();
    if (threadIdx.x == 0) {
        float t = red[0]+red[1]+red[2]+red[3]+red[4]+red[5]+red[6]+red[7];
        g_demod[b * CO + o] = rsqrtf(t + EPSV);
    }
}

// ---------------- prologue: x -> fp16, transpose, pad, k-half planes ----------------
__global__ __launch_bounds__(256) void prep_x_kernel(const float* __restrict__ x) {
    __shared__ float xs[16][132];
    const int t = threadIdx.x;
    const int h = blockIdx.x, ck = blockIdx.y, b = blockIdx.z;

    const float* src = x + ((size_t)(b * CI + ck * 16) * HH + h) * WW;
#pragma unroll
    for (int r = 0; r < 8; r++) {
        int idx = t + r * 256;
        int j = idx >> 7, pix = idx & 127;
        xs[j][pix] = src[(size_t)j * HH * WW + pix];
    }
    __syncthreads();

    __half2* dst = (__half2*)(g_xt + ((size_t)((b * CKN + ck) * HH + h)) * XROWH);
#pragma unroll
    for (int r = 0; r < 4; r++) {
        int o = t + r * 256;               // 0..1023: pix*8 + cpair p
        int pix = o >> 3, p = o & 7;
        int ci0 = p * 2;                   // plain k order
        int chalf = p >> 2, q = p & 3;
        dst[chalf * 520 + (pix + 1) * 4 + q] = __floats2half2_rn(xs[ci0][pix], xs[ci0 + 1][pix]);
    }
    if (t < 16) {   // zero borders: pix 0 and 129, both planes
        int side = t >> 3, p = t & 7;
        int chalf = p >> 2, q = p & 3;
        dst[chalf * 520 + (side ? 129 : 0) * 4 + q] = __floats2half2_rn(0.f, 0.f);
    }
}

// ---------------- prologue: modulated+demodulated fp16 weights (slot layout) --------
__global__ __launch_bounds__(128) void prep_w_kernel(
    const float* __restrict__ w, const float* __restrict__ y)
{
    const int ck = blockIdx.x, ct = blockIdx.y, b = blockIdx.z;
    const int co = threadIdx.x;
    const int o = ct * 128 + co;
    const float dd = g_demod[b * CO + o];
    __half2* blk = (__half2*)(g_weff + ((size_t)((b * 2 + ct) * CKN + ck)) * WH);
#pragma unroll
    for (int p = 0; p < 8; p++) {
        const int j0 = ((p >> 1) << 1) + ((p & 1) << 3);
        const int ci0 = ck * 16 + j0;
        const float m0 = (1.0f + y[b * CI + ci0]) * dd;
        const float m1 = (1.0f + y[b * CI + ci0 + 1]) * dd;
        const float* wp0 = w + ((size_t)o * CI + ci0) * 5;
        const float* wp1 = wp0 + 5;
#pragma unroll
        for (int tap = 0; tap < 5; tap++)
            blk[(tap * 128 + co) * 8 + p] = __floats2half2_rn(wp0[tap] * m0, wp1[tap] * m1);
    }
}

// ---------------- producer: one chunk into a stage ----------------
__device__ __forceinline__ void issue_chunk(
    int c, int h0, int b, int ct, uint32_t stage_dst, uint32_t full_mb)
{
    mbar_expect_tx(full_mb, TXBYTES);
    const __half* xb = g_xt + ((size_t)(b * CKN + c) * HH) * XROWH;
    if (h0 >= 2 && h0 <= 124) {
        bulk_g2s(stage_dst, xb + (size_t)(h0 - 1) * XROWH, 4 * XROWH * 2, full_mb);
    } else if (h0 == 0) {
        bulk_g2s(stage_dst, g_zero, XROWH * 2, full_mb);
        bulk_g2s(stage_dst + XROWH * 2, xb, 3 * XROWH * 2, full_mb);
    } else { // h0 == 126
        bulk_g2s(stage_dst, xb + (size_t)125 * XROWH, 3 * XROWH * 2, full_mb);
        bulk_g2s(stage_dst + 3 * XROWH * 2, g_zero, XROWH * 2, full_mb);
    }
    bulk_g2s(stage_dst + XH * 2,
             g_weff + ((size_t)((b * 2 + ct) * CKN + c)) * WH, WH * 2, full_mb);
}

// -- main: fp16 mma.sync, 16 compute warps (M64xN32) + 1 producer warp, 5 stages ------
__global__ __launch_bounds__(544, 1) void conv_mma_kernel(float* __restrict__ out) {
    extern __shared__ __half smem[];
    const uint32_t smem_base = smem_u32(smem);
    const uint32_t barbase = smem_base + NSTAGE * STAGEH * 2;

    const int tid  = threadIdx.x;
    const int lane = tid & 31;
    const int wid  = tid >> 5;
    const int grp  = lane >> 2;
    const int tig  = lane & 3;

    const int h0 = blockIdx.x * 2;
    const int ct = blockIdx.y;
    const int b  = blockIdx.z;

    if (tid == 0) {
        for (int s = 0; s < NSTAGE; s++) {
            mbar_init(barbase + s * 8, 1);                    // full
            mbar_init(barbase + NSTAGE * 8 + s * 8, 16);      // empty (per compute warp)
        }
        fence_async();
    }
    __syncthreads();

    if (wid == 16) {
        // ---------- dedicated producer warp ----------
        if (lane == 0) {
            for (int cc = 0; cc < CKN; cc++) {
                const int s = cc % NSTAGE;
                if (cc >= NSTAGE) {
                    const int r = (cc - NSTAGE) / NSTAGE;
                    mbar_wait(barbase + NSTAGE * 8 + s * 8, r & 1);
                }
                issue_chunk(cc, h0, b, ct, smem_base + s * STAGEH * 2, barbase + s * 8);
            }
        }
        return;
    }

    // ---------- compute warps: M64 x N32 ----------
    const int mg = wid >> 2;             // 0..3 : M64 tile over M=256
    const int ng = wid & 3;              // 0..3 : N32 tile over N=128
    const int row = mg >> 1;             // output row within CTA (0/1)
    const int pbase = (mg & 1) * 64;     // pixel base

    // ldmatrix lane offset: lanes 0-15 -> pixels (k-half 0), 16-31 -> k-half 1 plane
    const uint32_t loff = (uint32_t)((lane & 15) * 16 + (lane >> 4) * XPLANEB);

    float d[4][4][4];
#pragma unroll
    for (int f = 0; f < 4; f++)
#pragma unroll
        for (int nf = 0; nf < 4; nf++)
#pragma unroll
            for (int k = 0; k < 4; k++) d[f][nf][k] = 0.0f;

    for (int c = 0; c < CKN; c++) {
        const int s = c % NSTAGE;
        const int r = c / NSTAGE;
        mbar_wait(barbase + s * 8, r & 1);
        const uint32_t xs_u = smem_base + s * STAGEH * 2 + loff;
        const __half* ws = smem + s * STAGEH + XH;

#pragma unroll
        for (int tap = 0; tap < 5; tap++) {
            const int xrow  = row + ((tap == 0) ? 0 : (tap == 4 ? 2 : 1));
            const int shift = (tap == 1) ? -1 : ((tap == 3) ? 1 : 0);
            // warp-uniform base for this tap (padded pix index, 16 B per pixel)
            const uint32_t ub = xs_u + (uint32_t)(xrow * (XROWH * 2)
                              + (pbase + 1 + shift) * 16);
            uint32_t a[4][4];
#pragma unroll
            for (int f = 0; f < 4; f++)
                ldsm_x4(a[f], ub + (uint32_t)(f * 256));
            const __half* wb = ws + (tap * 128 + ng * 32 + grp) * 16 + tig * 4;
#pragma unroll
            for (int nf = 0; nf < 4; nf++) {
                const uint2 bv = *(const uint2*)(wb + nf * 128);
                mma16(d[0][nf], a[0], bv.x, bv.y);
                mma16(d[1][nf], a[1], bv.x, bv.y);
                mma16(d[2][nf], a[2], bv.x, bv.y);
                mma16(d[3][nf], a[3], bv.x, bv.y);
            }
        }
        if (lane == 0) mbar_arrive(barbase + NSTAGE * 8 + s * 8);
    }

    // ---- epilogue: demod folded into weights -> pure store ----
    float* ob = out + (((size_t)b * CO + ct * 128) * HH + (h0 + row)) * WW;
#pragma unroll
    for (int f = 0; f < 4; f++) {
        const int p = pbase + f * 16 + grp;
#pragma unroll
        for (int nf = 0; nf < 4; nf++) {
            const int co = ng * 32 + nf * 8 + tig * 2;
            ob[(size_t)co * (HH * WW) + p]           = d[f][nf][0];
            ob[(size_t)(co + 1) * (HH * WW) + p]     = d[f][nf][1];
            ob[(size_t)co * (HH * WW) + p + 8]       = d[f][nf][2];
            ob[(size_t)(co + 1) * (HH * WW) + p + 8] = d[f][nf][3];
        }
    }
}

extern "C" void kernel_launch(void* const* d_in, const int* in_sizes, int n_in,
                              void* d_out, int out_size) {
    const float* x = (const float*)d_in[0];
    const float* y = (const float*)d_in[1];
    const float* w = (const float*)d_in[2];
    float* out = (float*)d_out;

    cudaFuncSetAttribute(conv_mma_kernel, cudaFuncAttributeMaxDynamicSharedMemorySize, SMEM_DYN);

    demod_kernel<<<dim3(CO, BS), 256>>>(y, w);
    prep_x_kernel<<<dim3(HH, CKN, BS), 256>>>(x);
    prep_w_kernel<<<dim3(CKN, 2, BS), 128>>>(w, y);
    conv_mma_kernel<<<dim3(HH / 2, 2, BS), 544, SMEM_DYN>>>(out);
}

// round 13
// speedup vs baseline: 1.2281x; 1.0544x over previous
#include <cuda_runtime.h>
#include <cuda_fp16.h>
#include <cstdint>
#include <cstddef>

#define BS 8
#define CI 256
#define CO 256
#define HH 128
#define WW 128
#define EPSV 1e-6f

#define CKN 16                    // ci chunks of 16
// Stage layout (halves):
//  X: [xrow 4][chalf 2][pix 130][8 halves] = 8320 halves (16640 B)
//  W: [tap 5][khalf 2][co 128][8 halves]   = 10240 halves (20480 B)
#define XROWH 2080                // one xrow: 2 planes x 130 x 8
#define XPLANEB 2080              // one chalf plane in BYTES: 130*16
#define XH (4 * XROWH)            // 8320
#define WH 10240
#define STAGEH (XH + WH)          // 18560 halves = 37120 B
#define NSTAGE 5
#define TXBYTES (STAGEH * 2)
#define SMEM_DYN (NSTAGE * STAGEH * 2 + 256)

// ---------------- device scratch (no cudaMalloc allowed) ----------------
// x: fp16, padded: block (b*16+ck)*128+h of 2080 halves: [chalf 2][pix 0..129][8 halves]
__device__ __align__(16) __half g_xt[(size_t)BS * CKN * HH * XROWH];
// w_eff = fp16(w * (1+y) * demod): block ((b*2+ct)*16+ck): [tap][khalf][co][8 halves]
__device__ __align__(16) __half g_weff[(size_t)BS * 2 * CKN * WH];
__device__ float g_demod[BS * CO];
__device__ __align__(16) __half g_zero[XROWH];   // zero halo row (.bss)

// ---------------- PTX helpers (base sm_103 legal; NO tcgen05) ----------------
__device__ __forceinline__ uint32_t smem_u32(const void* p) {
    uint32_t a;
    asm("{ .reg .u64 t; cvta.to.shared.u64 t, %1; cvt.u32.u64 %0, t; }" : "=r"(a) : "l"(p));
    return a;
}
__device__ __forceinline__ void mbar_init(uint32_t mbar, uint32_t cnt) {
    asm volatile("mbarrier.init.shared.b64 [%0], %1;" :: "r"(mbar), "r"(cnt) : "memory");
}
__device__ __forceinline__ void mbar_expect_tx(uint32_t mbar, uint32_t bytes) {
    asm volatile("mbarrier.arrive.expect_tx.shared.b64 _, [%0], %1;"
                 :: "r"(mbar), "r"(bytes) : "memory");
}
__device__ __forceinline__ void mbar_arrive(uint32_t mbar) {
    asm volatile("mbarrier.arrive.shared.b64 _, [%0];" :: "r"(mbar) : "memory");
}
__device__ __forceinline__ void mbar_wait(uint32_t mbar, uint32_t parity) {
    asm volatile(
        "{\n\t.reg .pred P;\n\t"
        "WL_%=:\n\t"
        "mbarrier.try_wait.parity.acquire.cta.shared::cta.b64 P, [%0], %1, 0x989680;\n\t"
        "@P bra.uni WD_%=;\n\t"
        "bra.uni WL_%=;\n\t"
        "WD_%=:\n\t}"
        :: "r"(mbar), "r"(parity) : "memory");
}
__device__ __forceinline__ void bulk_g2s(uint32_t dst, const void* src, uint32_t bytes, uint32_t mbar) {
    asm volatile(
        "cp.async.bulk.shared::cluster.global.mbarrier::complete_tx::bytes [%0], [%1], %2, [%3];"
        :: "r"(dst), "l"(src), "r"(bytes), "r"(mbar) : "memory");
}
__device__ __forceinline__ void fence_async() {
    asm volatile("fence.proxy.async.shared::cta;" ::: "memory");
}
// ldmatrix x4 (canonical m8n8 tiles)
__device__ __forceinline__ void ldsm_x4(uint32_t* r, uint32_t addr) {
    asm volatile("ldmatrix.sync.aligned.m8n8.x4.shared.b16 {%0,%1,%2,%3}, [%4];"
                 : "=r"(r[0]), "=r"(r[1]), "=r"(r[2]), "=r"(r[3]) : "r"(addr));
}
// m16n8k16 fp16 MMA, fp32 accumulate
__device__ __forceinline__ void mma16(float* d, const uint32_t* a, uint32_t b0, uint32_t b1) {
    asm volatile(
        "mma.sync.aligned.m16n8k16.row.col.f32.f16.f16.f32 "
        "{%0,%1,%2,%3}, {%4,%5,%6,%7}, {%8,%9}, {%0,%1,%2,%3};"
        : "+f"(d[0]), "+f"(d[1]), "+f"(d[2]), "+f"(d[3])
        : "r"(a[0]), "r"(a[1]), "r"(a[2]), "r"(a[3]), "r"(b0), "r"(b1));
}

// ---------------- prologue: demod ----------------
__global__ void demod_kernel(const float* __restrict__ y, const float* __restrict__ w) {
    int o = blockIdx.x, b = blockIdx.y, ci = threadIdx.x;
    float m = 1.0f + y[b * CI + ci];
    const float* wr = w + ((size_t)o * CI + ci) * 5;
    float s = wr[0]*wr[0] + wr[1]*wr[1] + wr[2]*wr[2] + wr[3]*wr[3] + wr[4]*wr[4];
    float v = m * m * s;
#pragma unroll
    for (int off = 16; off; off >>= 1) v += __shfl_xor_sync(0xffffffffu, v, off);
    __shared__ float red[8];
    if ((threadIdx.x & 31) == 0) red[threadIdx.x >> 5] = v;
    __syncthreads();
    if (threadIdx.x == 0) {
        float t = red[0]+red[1]+red[2]+red[3]+red[4]+red[5]+red[6]+red[7];
        g_demod[b * CO + o] = rsqrtf(t + EPSV);
    }
}

// ---------------- prologue: x -> fp16, transpose, pad, k-half planes ----------------
__global__ __launch_bounds__(256) void prep_x_kernel(const float* __restrict__ x) {
    __shared__ float xs[16][132];
    const int t = threadIdx.x;
    const int h = blockIdx.x, ck = blockIdx.y, b = blockIdx.z;

    const float* src = x + ((size_t)(b * CI + ck * 16) * HH + h) * WW;
#pragma unroll
    for (int r = 0; r < 8; r++) {
        int idx = t + r * 256;
        int j = idx >> 7, pix = idx & 127;
        xs[j][pix] = src[(size_t)j * HH * WW + pix];
    }
    __syncthreads();

    __half2* dst = (__half2*)(g_xt + ((size_t)((b * CKN + ck) * HH + h)) * XROWH);
#pragma unroll
    for (int r = 0; r < 4; r++) {
        int o = t + r * 256;               // 0..1023: pix*8 + cpair p
        int pix = o >> 3, p = o & 7;
        int ci0 = p * 2;                   // plain k order
        int chalf = p >> 2, q = p & 3;
        dst[chalf * 520 + (pix + 1) * 4 + q] = __floats2half2_rn(xs[ci0][pix], xs[ci0 + 1][pix]);
    }
    if (t < 16) {   // zero borders: pix 0 and 129, both planes
        int side = t >> 3, p = t & 7;
        int chalf = p >> 2, q = p & 3;
        dst[chalf * 520 + (side ? 129 : 0) * 4 + q] = __floats2half2_rn(0.f, 0.f);
    }
}

// ---------------- prologue: weights -> [tap][khalf][co][8 halves] ----------
__global__ __launch_bounds__(128) void prep_w_kernel(
    const float* __restrict__ w, const float* __restrict__ y)
{
    const int ck = blockIdx.x, ct = blockIdx.y, b = blockIdx.z;
    const int co = threadIdx.x;
    const int o = ct * 128 + co;
    const float dd = g_demod[b * CO + o];
    __half2* blk = (__half2*)(g_weff + ((size_t)((b * 2 + ct) * CKN + ck)) * WH);
#pragma unroll
    for (int kh = 0; kh < 2; kh++) {
#pragma unroll
        for (int j2 = 0; j2 < 4; j2++) {
            const int ci0 = ck * 16 + kh * 8 + j2 * 2;
            const float m0 = (1.0f + y[b * CI + ci0]) * dd;
            const float m1 = (1.0f + y[b * CI + ci0 + 1]) * dd;
            const float* wp0 = w + ((size_t)o * CI + ci0) * 5;
            const float* wp1 = wp0 + 5;
#pragma unroll
            for (int tap = 0; tap < 5; tap++)
                blk[((tap * 2 + kh) * 128 + co) * 4 + j2] =
                    __floats2half2_rn(wp0[tap] * m0, wp1[tap] * m1);
        }
    }
}

// ---------------- producer: one chunk into a stage ----------------
__device__ __forceinline__ void issue_chunk(
    int c, int h0, int b, int ct, uint32_t stage_dst, uint32_t full_mb)
{
    mbar_expect_tx(full_mb, TXBYTES);
    const __half* xb = g_xt + ((size_t)(b * CKN + c) * HH) * XROWH;
    if (h0 >= 2 && h0 <= 124) {
        bulk_g2s(stage_dst, xb + (size_t)(h0 - 1) * XROWH, 4 * XROWH * 2, full_mb);
    } else if (h0 == 0) {
        bulk_g2s(stage_dst, g_zero, XROWH * 2, full_mb);
        bulk_g2s(stage_dst + XROWH * 2, xb, 3 * XROWH * 2, full_mb);
    } else { // h0 == 126
        bulk_g2s(stage_dst, xb + (size_t)125 * XROWH, 3 * XROWH * 2, full_mb);
        bulk_g2s(stage_dst + 3 * XROWH * 2, g_zero, XROWH * 2, full_mb);
    }
    bulk_g2s(stage_dst + XH * 2,
             g_weff + ((size_t)((b * 2 + ct) * CKN + c)) * WH, WH * 2, full_mb);
}

// ---------------- chunk body (templated tap order for desync) ----------------
template <bool REV>
__device__ __forceinline__ void do_chunk(
    float (&d)[4][4][4], uint32_t xs_u, uint32_t ws_u, int row, int pbase)
{
#pragma unroll
    for (int ti = 0; ti < 5; ti++) {
        const int tap   = REV ? (4 - ti) : ti;
        const int xrow  = row + ((tap == 0) ? 0 : (tap == 4 ? 2 : 1));
        const int shift = (tap == 1) ? -1 : ((tap == 3) ? 1 : 0);
        const uint32_t ub = xs_u + (uint32_t)(xrow * (XROWH * 2)
                          + (pbase + 1 + shift) * 16);
        uint32_t a[4][4];
#pragma unroll
        for (int f = 0; f < 4; f++)
            ldsm_x4(a[f], ub + (uint32_t)(f * 256));
        // B: two ldsm.x4, each = {b0,b1} for nf pair
        uint32_t bp0[4], bp1[4];
        ldsm_x4(bp0, ws_u + (uint32_t)(tap * 4096));
        ldsm_x4(bp1, ws_u + (uint32_t)(tap * 4096 + 256));
#pragma unroll
        for (int f = 0; f < 4; f++) {
            mma16(d[f][0], a[f], bp0[0], bp0[1]);
            mma16(d[f][1], a[f], bp0[2], bp0[3]);
            mma16(d[f][2], a[f], bp1[0], bp1[1]);
            mma16(d[f][3], a[f], bp1[2], bp1[3]);
        }
    }
}

// -- main: fp16 mma.sync, 16 compute warps (M64xN32, staggered) + producer warp -------
__global__ __launch_bounds__(544, 1) void conv_mma_kernel(float* __restrict__ out) {
    extern __shared__ __half smem[];
    const uint32_t smem_base = smem_u32(smem);
    const uint32_t barbase = smem_base + NSTAGE * STAGEH * 2;

    const int tid  = threadIdx.x;
    const int lane = tid & 31;
    const int wid  = tid >> 5;
    const int grp  = lane >> 2;
    const int tig  = lane & 3;

    const int h0 = blockIdx.x * 2;
    const int ct = blockIdx.y;
    const int b  = blockIdx.z;

    if (tid == 0) {
        for (int s = 0; s < NSTAGE; s++) {
            mbar_init(barbase + s * 8, 1);                    // full
            mbar_init(barbase + NSTAGE * 8 + s * 8, 16);      // empty (per compute warp)
        }
        fence_async();
    }
    __syncthreads();

    if (wid == 16) {
        // ---------- dedicated producer warp ----------
        if (lane == 0) {
            for (int cc = 0; cc < CKN; cc++) {
                const int s = cc % NSTAGE;
                if (cc >= NSTAGE) {
                    const int r = (cc - NSTAGE) / NSTAGE;
                    mbar_wait(barbase + NSTAGE * 8 + s * 8, r & 1);
                }
                issue_chunk(cc, h0, b, ct, smem_base + s * STAGEH * 2, barbase + s * 8);
            }
        }
        return;
    }

    // ---------- compute warps: M64 x N32 ----------
    const int mg = wid >> 2;             // 0..3 : M64 tile over M=256
    const int ng = wid & 3;              // 0..3 : N32 tile over N=128
    const int row = mg >> 1;             // output row within CTA (0/1)
    const int pbase = (mg & 1) * 64;     // pixel base

    // A ldmatrix lane offset: lanes 0-15 -> pixels (k-half 0), 16-31 -> k-half 1 plane
    const uint32_t loff = (uint32_t)((lane & 15) * 16 + (lane >> 4) * XPLANEB);
    // B ldmatrix lane offset: m0=nf(kh0) m1=nf(kh1) m2=nf+1(kh0) m3=nf+1(kh1)
    const uint32_t wloff = (uint32_t)((lane & 7) * 16 + ((lane >> 3) & 1) * 2048
                         + (lane >> 4) * 128);

    float d[4][4][4];
#pragma unroll
    for (int f = 0; f < 4; f++)
#pragma unroll
        for (int nf = 0; nf < 4; nf++)
#pragma unroll
            for (int k = 0; k < 4; k++) d[f][nf][k] = 0.0f;

    for (int c = 0; c < CKN; c++) {
        const int s = c % NSTAGE;
        const int r = c / NSTAGE;
        mbar_wait(barbase + s * 8, r & 1);
        const uint32_t xs_u = smem_base + s * STAGEH * 2 + loff;
        const uint32_t ws_u = smem_base + s * STAGEH * 2 + XH * 2
                            + (uint32_t)(ng * 512) + wloff;

        if (mg & 1) do_chunk<true >(d, xs_u, ws_u, row, pbase);
        else        do_chunk<false>(d, xs_u, ws_u, row, pbase);

        if (lane == 0) mbar_arrive(barbase + NSTAGE * 8 + s * 8);
    }

    // ---- epilogue: demod folded into weights -> pure store ----
    float* ob = out + (((size_t)b * CO + ct * 128) * HH + (h0 + row)) * WW;
#pragma unroll
    for (int f = 0; f < 4; f++) {
        const int p = pbase + f * 16 + grp;
#pragma unroll
        for (int nf = 0; nf < 4; nf++) {
            const int co = ng * 32 + nf * 8 + tig * 2;
            ob[(size_t)co * (HH * WW) + p]           = d[f][nf][0];
            ob[(size_t)(co + 1) * (HH * WW) + p]     = d[f][nf][1];
            ob[(size_t)co * (HH * WW) + p + 8]       = d[f][nf][2];
            ob[(size_t)(co + 1) * (HH * WW) + p + 8] = d[f][nf][3];
        }
    }
}

extern "C" void kernel_launch(void* const* d_in, const int* in_sizes, int n_in,
                              void* d_out, int out_size) {
    const float* x = (const float*)d_in[0];
    const float* y = (const float*)d_in[1];
    const float* w = (const float*)d_in[2];
    float* out = (float*)d_out;

    cudaFuncSetAttribute(conv_mma_kernel, cudaFuncAttributeMaxDynamicSharedMemorySize, SMEM_DYN);

    demod_kernel<<<dim3(CO, BS), 256>>>(y, w);
    prep_x_kernel<<<dim3(HH, CKN, BS), 256>>>(x);
    prep_w_kernel<<<dim3(CKN, 2, BS), 128>>>(w, y);
    conv_mma_kernel<<<dim3(HH / 2, 2, BS), 544, SMEM_DYN>>>(out);
}